// round 15
// baseline (speedup 1.0000x reference)
#include <cuda_runtime.h>
#include <cstdint>

// ---------------------------------------------------------------------------
// Problem constants
// ---------------------------------------------------------------------------
#define NTOK   256
#define DIM    4096
#define HIDDEN 14336
#define KVDIM  1024
#define NHEAD  32
#define HDIM   128
#define TSTEPS 10

typedef unsigned long long u64;

// ---------------------------------------------------------------------------
// Packed f32x2 helpers (sm_103a FFMA2 path — only reachable via PTX).
// ---------------------------------------------------------------------------
__device__ __forceinline__ u64 fdup(float a) {
    u64 r; asm("mov.b64 %0, {%1, %1};" : "=l"(r) : "f"(a)); return r;
}
__device__ __forceinline__ void ffma2(u64& d, u64 a, u64 b) {
    asm("fma.rn.f32x2 %0, %1, %2, %0;" : "+l"(d) : "l"(a), "l"(b));
}
__device__ __forceinline__ void fadd2(u64& d, u64 a) {
    asm("add.rn.f32x2 %0, %0, %1;" : "+l"(d) : "l"(a));
}
__device__ __forceinline__ float2 funpack(u64 v) {
    float lo, hi; asm("mov.b64 {%0, %1}, %2;" : "=f"(lo), "=f"(hi) : "l"(v));
    return make_float2(lo, hi);
}

// ---------------------------------------------------------------------------
// Scratch (device globals)
// ---------------------------------------------------------------------------
__device__ float    g_xs [2 * NTOK * DIM];
__device__ float    g_hs [2 * NTOK * DIM];
__device__ unsigned g_qm [2 * NTOK * DIM];
__device__ unsigned g_km [2 * NTOK * KVDIM];
__device__ unsigned g_vm [2 * NTOK * KVDIM];
__device__ float    g_xat[TSTEPS * NTOK * DIM];
__device__ float    g_yt [TSTEPS * NTOK * DIM];
__device__ float    g_h  [NTOK * DIM];
__device__ float    g_c3 [2 * NTOK * HIDDEN];
__device__ float    g_c1 [NTOK * HIDDEN];
__device__ float    g_gate[NTOK * HIDDEN];

// ---------------------------------------------------------------------------
// RMSNorm + stacked relu (bit-frozen)
// ---------------------------------------------------------------------------
__global__ __launch_bounds__(1024)
void rmsnorm_relu_kernel(const float* __restrict__ x,
                         const float* __restrict__ w,
                         float* __restrict__ out)
{
    const int n = blockIdx.x;
    const int t = threadIdx.x;
    const float* xr = x + (size_t)n * DIM;

    float acc = 0.f;
    #pragma unroll
    for (int i = 0; i < 2; i++) {
        float2 v = *(const float2*)(xr + 2 * t + i * 2048);
        acc += v.x * v.x;
        acc += v.y * v.y;
    }
    #pragma unroll
    for (int o = 16; o > 0; o >>= 1)
        acc += __shfl_down_sync(0xffffffffu, acc, o);

    __shared__ float sw[32];
    __shared__ float sres;
    const int lane = t & 31, wid = t >> 5;
    if (lane == 0) sw[wid] = acc;
    __syncthreads();
    if (wid == 0) {
        float v = sw[lane];
        #pragma unroll
        for (int o = 16; o > 0; o >>= 1)
            v += __shfl_down_sync(0xffffffffu, v, o);
        if (lane == 0) sres = v;
    }
    __syncthreads();

    const float rs = rsqrtf(sres * (1.0f / 4096.0f) + 1e-5f);
    #pragma unroll
    for (int i = 0; i < 4; i++) {
        const int c = t + i * 1024;
        float v = xr[c] * rs * w[c];
        out[(size_t)n * DIM + c]          = fmaxf(v, 0.f);
        out[(size_t)(n + NTOK) * DIM + c] = fmaxf(-v, 0.f);
    }
}

// ---------------------------------------------------------------------------
// QKV GEMM: split-K=4 emulation, FFMA2 (exact R12 form — bit-frozen).
// ---------------------------------------------------------------------------
#define QBM 128
#define QBN 64
#define QBK 16
#define SPLITK_CHUNK 1024

__global__ __launch_bounds__(256, 2)
void gemm_qkv_kernel(const float* __restrict__ A,
                     const float* __restrict__ B0,
                     const float* __restrict__ B1,
                     const float* __restrict__ B2,
                     unsigned* __restrict__ C0, unsigned* __restrict__ C1,
                     unsigned* __restrict__ C2, int K)
{
    __shared__ float As[2][QBK][QBM];
    __shared__ float Bs[2][QBK][QBN];

    const int bx = blockIdx.x, by = blockIdx.y;
    const float* B; unsigned* C; int N, bxl;
    const int row0 = by * QBM;
    if (bx < 64)      { B = B0; C = C0; N = DIM;   bxl = bx; }
    else if (bx < 80) { B = B1; C = C1; N = KVDIM; bxl = bx - 64; }
    else              { B = B2; C = C2; N = KVDIM; bxl = bx - 80; }

    const int tid = threadIdx.x;
    const int tx = tid & 15;
    const int ty = tid >> 4;

    const int lrowA = tid >> 1;
    const int lcolA = (tid & 1) * 8;
    const int lrowB = tid >> 2;
    const int lcolB = (tid & 3) * 4;

    const float* Aptr = A + (size_t)(row0 + lrowA) * K + lcolA;
    const float* Bptr = B + (size_t)(bxl * QBN + lrowB) * K + lcolB;

    u64 acc2[8][2], tot2[8][2];
    #pragma unroll
    for (int i = 0; i < 8; i++)
        #pragma unroll
        for (int j = 0; j < 2; j++) { acc2[i][j] = 0ULL; tot2[i][j] = 0ULL; }

    float4 a0s, a1s, b0s;
    #define QLOAD()                                                            \
        do {                                                                   \
            a0s = *(const float4*)Aptr;                                        \
            a1s = *(const float4*)(Aptr + 4);                                  \
            b0s = *(const float4*)Bptr;                                        \
            Aptr += QBK; Bptr += QBK;                                          \
        } while (0)
    #define QSTORE(BUF)                                                        \
        do {                                                                   \
            As[BUF][lcolA + 0][lrowA] = a0s.x; As[BUF][lcolA + 1][lrowA] = a0s.y; \
            As[BUF][lcolA + 2][lrowA] = a0s.z; As[BUF][lcolA + 3][lrowA] = a0s.w; \
            As[BUF][lcolA + 4][lrowA] = a1s.x; As[BUF][lcolA + 5][lrowA] = a1s.y; \
            As[BUF][lcolA + 6][lrowA] = a1s.z; As[BUF][lcolA + 7][lrowA] = a1s.w; \
            Bs[BUF][lcolB + 0][lrowB] = b0s.x; Bs[BUF][lcolB + 1][lrowB] = b0s.y; \
            Bs[BUF][lcolB + 2][lrowB] = b0s.z; Bs[BUF][lcolB + 3][lrowB] = b0s.w; \
        } while (0)

    QLOAD(); QSTORE(0);
    __syncthreads();

    int buf = 0;
    for (int k0 = 0; k0 < K; k0 += QBK) {
        const bool has_next = (k0 + QBK < K);
        if (has_next) QLOAD();

        #pragma unroll
        for (int kk = 0; kk < QBK; kk++) {
            float4 a0 = *(const float4*)&As[buf][kk][ty * 8];
            float4 a1 = *(const float4*)&As[buf][kk][ty * 8 + 4];
            ulonglong2 bp = *(const ulonglong2*)&Bs[buf][kk][tx * 4];
            u64 b_pk[2] = { bp.x, bp.y };
            u64 a_pk[8] = { fdup(a0.x), fdup(a0.y), fdup(a0.z), fdup(a0.w),
                            fdup(a1.x), fdup(a1.y), fdup(a1.z), fdup(a1.w) };
            #pragma unroll
            for (int i = 0; i < 8; i++)
                #pragma unroll
                for (int jp = 0; jp < 2; jp++)
                    ffma2(acc2[i][jp], a_pk[i], b_pk[jp]);
        }

        if (((k0 + QBK) & (SPLITK_CHUNK - 1)) == 0) {
            #pragma unroll
            for (int i = 0; i < 8; i++)
                #pragma unroll
                for (int jp = 0; jp < 2; jp++) {
                    fadd2(tot2[i][jp], acc2[i][jp]);
                    acc2[i][jp] = 0ULL;
                }
        }

        if (has_next) QSTORE(buf ^ 1);
        __syncthreads();
        buf ^= 1;
    }
    #undef QLOAD
    #undef QSTORE

    #pragma unroll
    for (int i = 0; i < 8; i++) {
        const int r = row0 + ty * 8 + i;
        #pragma unroll
        for (int jp = 0; jp < 2; jp++) {
            float2 yv = funpack(tot2[i][jp]);
            #pragma unroll
            for (int l = 0; l < 2; l++) {
                const int col = bxl * QBN + tx * 4 + jp * 2 + l;
                float y = (l == 0) ? yv.x : yv.y;
                unsigned m = 0; float vm = 0.f;
                #pragma unroll
                for (int t = 0; t < TSTEPS; t++) {
                    vm += y;
                    if (vm - 1.0f >= 0.f) { m |= (1u << t); vm = 0.f; }
                }
                C[(size_t)r * N + col] = m;
            }
        }
    }
}

// ---------------------------------------------------------------------------
// Big GEMM (NT), 128x128 tile, 8x8/thread, BK=32 (two-pass staging, halved
// barriers), DYNAMIC double-buffered smem (64KB), FFMA2, split frags +
// frag pipelining. kk strictly ascending per output -> bit-exact vs R12.
//   MODE 1: FFN spike counts (N=HIDDEN; by<4 -> w3/c3 M=512; else w1/c1 M=256)
//   MODE 2: plain f32 store (per-t wo GEMM, M=2560, N=DIM)
// ---------------------------------------------------------------------------
#define BM2  128
#define BN2  128
#define BK2G 32
#define BKH  16   // half-chunk (staging granularity)

template<int MODE>
__global__ __launch_bounds__(256, 2)
void gemm2_kernel(const float* __restrict__ A,
                  const float* __restrict__ B0,
                  const float* __restrict__ B1,
                  void* __restrict__ C0, void* __restrict__ C1, int K)
{
    extern __shared__ float dsm[];
    float (*As)[BK2G][BM2] = (float(*)[BK2G][BM2])dsm;                    // [2][32][128]
    float (*Bs)[BK2G][BN2] = (float(*)[BK2G][BN2])(dsm + 2 * BK2G * BM2); // [2][32][128]

    const int bx = blockIdx.x, by = blockIdx.y;
    const float* B; void* C; int N, row0;
    if (MODE == 1) {
        N = HIDDEN;
        if (by < 4) { B = B0; C = C0; row0 = by * BM2; }
        else        { B = B1; C = C1; row0 = (by - 4) * BM2; }
    } else {
        N = DIM; B = B0; C = C0; row0 = by * BM2;
    }

    const int tid = threadIdx.x;
    const int tx = tid & 15;
    const int ty = tid >> 4;
    const int lrow = tid >> 1;
    const int lcol = (tid & 1) * 8;

    const float* Aptr = A + (size_t)(row0 + lrow) * K + lcol;
    const float* Bptr = B + (size_t)(bx * BN2 + lrow) * K + lcol;

    u64 acc2[8][4];
    #pragma unroll
    for (int i = 0; i < 8; i++)
        #pragma unroll
        for (int jp = 0; jp < 4; jp++) acc2[i][jp] = 0ULL;

    float4 a0s, a1s, b0s, b1s;
    // load HALF a chunk (16 k) into staging; pointers advance by 16
    #define GLOADH()                                                           \
        do {                                                                   \
            a0s = *(const float4*)Aptr;                                        \
            a1s = *(const float4*)(Aptr + 4);                                  \
            b0s = *(const float4*)Bptr;                                        \
            b1s = *(const float4*)(Bptr + 4);                                  \
            Aptr += BKH; Bptr += BKH;                                          \
        } while (0)
    // store staging into half H (0 or 1) of buffer BUF
    #define GSTOREH(BUF, H)                                                    \
        do {                                                                   \
            const int kb = (H) * BKH + lcol;                                   \
            As[BUF][kb + 0][lrow] = a0s.x; As[BUF][kb + 1][lrow] = a0s.y;      \
            As[BUF][kb + 2][lrow] = a0s.z; As[BUF][kb + 3][lrow] = a0s.w;      \
            As[BUF][kb + 4][lrow] = a1s.x; As[BUF][kb + 5][lrow] = a1s.y;      \
            As[BUF][kb + 6][lrow] = a1s.z; As[BUF][kb + 7][lrow] = a1s.w;      \
            Bs[BUF][kb + 0][lrow] = b0s.x; Bs[BUF][kb + 1][lrow] = b0s.y;      \
            Bs[BUF][kb + 2][lrow] = b0s.z; Bs[BUF][kb + 3][lrow] = b0s.w;      \
            Bs[BUF][kb + 4][lrow] = b1s.x; Bs[BUF][kb + 5][lrow] = b1s.y;      \
            Bs[BUF][kb + 6][lrow] = b1s.z; Bs[BUF][kb + 7][lrow] = b1s.w;      \
        } while (0)

    float4     fa0[2], fa1[2];
    ulonglong2 fb0[2], fb1[2];
    #define FRAG_LOAD(P, BUF, KK)                                              \
        do {                                                                   \
            fa0[P] = *(const float4*)&As[BUF][KK][ty * 4];                     \
            fa1[P] = *(const float4*)&As[BUF][KK][64 + ty * 4];                \
            fb0[P] = *(const ulonglong2*)&Bs[BUF][KK][tx * 4];                 \
            fb1[P] = *(const ulonglong2*)&Bs[BUF][KK][64 + tx * 4];            \
        } while (0)
    #define DOFMA(P)                                                           \
        do {                                                                   \
            u64 b_pk[4] = { fb0[P].x, fb0[P].y, fb1[P].x, fb1[P].y };          \
            u64 a_pk[8] = { fdup(fa0[P].x), fdup(fa0[P].y),                    \
                            fdup(fa0[P].z), fdup(fa0[P].w),                    \
                            fdup(fa1[P].x), fdup(fa1[P].y),                    \
                            fdup(fa1[P].z), fdup(fa1[P].w) };                  \
            _Pragma("unroll")                                                  \
            for (int i = 0; i < 8; i++)                                        \
                _Pragma("unroll")                                              \
                for (int jp = 0; jp < 4; jp++)                                 \
                    ffma2(acc2[i][jp], a_pk[i], b_pk[jp]);                     \
        } while (0)

    // preload chunk 0 (both halves)
    GLOADH(); GSTOREH(0, 0);
    GLOADH(); GSTOREH(0, 1);
    __syncthreads();

    int buf = 0;
    for (int k0 = 0; k0 < K; k0 += BK2G) {
        const bool has_next = (k0 + BK2G < K);

        if (has_next) GLOADH();          // next chunk, half 0

        FRAG_LOAD(0, buf, 0);
        #pragma unroll
        for (int kk = 0; kk < BKH; kk++) {
            const int p = kk & 1;
            FRAG_LOAD(p ^ 1, buf, kk + 1);   // kk+1 <= 16 < 32, always valid
            DOFMA(p);
        }

        if (has_next) { GSTOREH(buf ^ 1, 0); GLOADH(); }   // store h0, load h1

        #pragma unroll
        for (int kk = BKH; kk < BK2G; kk++) {
            const int p = kk & 1;
            if (kk + 1 < BK2G) FRAG_LOAD(p ^ 1, buf, kk + 1);
            DOFMA(p);
        }

        if (has_next) GSTOREH(buf ^ 1, 1);
        __syncthreads();
        buf ^= 1;
    }
    #undef GLOADH
    #undef GSTOREH
    #undef FRAG_LOAD
    #undef DOFMA

    #pragma unroll
    for (int i = 0; i < 8; i++) {
        const int r = row0 + ((i < 4) ? (ty * 4 + i) : (64 + ty * 4 + (i - 4)));
        #pragma unroll
        for (int jp = 0; jp < 4; jp++) {
            const int colbase = bx * BN2 +
                ((jp < 2) ? (tx * 4 + jp * 2) : (64 + tx * 4 + (jp - 2) * 2));
            float2 yv = funpack(acc2[i][jp]);
            #pragma unroll
            for (int l = 0; l < 2; l++) {
                const size_t idx = (size_t)r * N + colbase + l;
                float y = (l == 0) ? yv.x : yv.y;
                if (MODE == 1) {
                    int cnt = 0; float vm = 0.f;
                    #pragma unroll
                    for (int t = 0; t < TSTEPS; t++) {
                        vm += y;
                        if (vm - 1.0f >= 0.f) { cnt++; vm = 0.f; }
                    }
                    ((float*)C)[idx] = (float)cnt;
                } else {
                    ((float*)C)[idx] = y;
                }
            }
        }
    }
}

// ---------------------------------------------------------------------------
// w2 GEMM: 64x64 tile (256 CTAs), BK=32, 4x4/thread, FFMA2, frag-pipelined.
// ---------------------------------------------------------------------------
#define WBM 64
#define WBN 64
#define WBK 32

__global__ __launch_bounds__(256)
void gemm_w2_kernel(const float* __restrict__ A,
                    const float* __restrict__ B,
                    float* __restrict__ C,
                    const float* __restrict__ addv, int K)
{
    __shared__ float As[2][WBK][WBM];
    __shared__ float Bs[2][WBK][WBN];

    const int bx = blockIdx.x, by = blockIdx.y;
    const int row0 = by * WBM;
    const int tid = threadIdx.x;
    const int tx = tid & 15;
    const int ty = tid >> 4;
    const int lrow = tid >> 2;
    const int lcol = (tid & 3) * 8;

    const float* Aptr = A + (size_t)(row0 + lrow) * K + lcol;
    const float* Bptr = B + (size_t)(bx * WBN + lrow) * K + lcol;

    u64 acc2[4][2];
    #pragma unroll
    for (int i = 0; i < 4; i++)
        #pragma unroll
        for (int jp = 0; jp < 2; jp++) acc2[i][jp] = 0ULL;

    float4 a0s, a1s, b0s, b1s;
    #define WLOAD()                                                            \
        do {                                                                   \
            a0s = *(const float4*)Aptr;                                        \
            a1s = *(const float4*)(Aptr + 4);                                  \
            b0s = *(const float4*)Bptr;                                        \
            b1s = *(const float4*)(Bptr + 4);                                  \
            Aptr += WBK; Bptr += WBK;                                          \
        } while (0)
    #define WSTORE(BUF)                                                        \
        do {                                                                   \
            As[BUF][lcol + 0][lrow] = a0s.x; As[BUF][lcol + 1][lrow] = a0s.y;  \
            As[BUF][lcol + 2][lrow] = a0s.z; As[BUF][lcol + 3][lrow] = a0s.w;  \
            As[BUF][lcol + 4][lrow] = a1s.x; As[BUF][lcol + 5][lrow] = a1s.y;  \
            As[BUF][lcol + 6][lrow] = a1s.z; As[BUF][lcol + 7][lrow] = a1s.w;  \
            Bs[BUF][lcol + 0][lrow] = b0s.x; Bs[BUF][lcol + 1][lrow] = b0s.y;  \
            Bs[BUF][lcol + 2][lrow] = b0s.z; Bs[BUF][lcol + 3][lrow] = b0s.w;  \
            Bs[BUF][lcol + 4][lrow] = b1s.x; Bs[BUF][lcol + 5][lrow] = b1s.y;  \
            Bs[BUF][lcol + 6][lrow] = b1s.z; Bs[BUF][lcol + 7][lrow] = b1s.w;  \
        } while (0)

    float4     wa[2];
    ulonglong2 wb[2];
    #define WFRAG(P, BUF, KK)                                                  \
        do {                                                                   \
            wa[P] = *(const float4*)&As[BUF][KK][ty * 4];                      \
            wb[P] = *(const ulonglong2*)&Bs[BUF][KK][tx * 4];                  \
        } while (0)

    WLOAD(); WSTORE(0);
    __syncthreads();

    int buf = 0;
    for (int k0 = 0; k0 < K; k0 += WBK) {
        const bool has_next = (k0 + WBK < K);
        if (has_next) WLOAD();

        WFRAG(0, buf, 0);
        #pragma unroll
        for (int kk = 0; kk < WBK; kk++) {
            const int p = kk & 1;
            if (kk + 1 < WBK) WFRAG(p ^ 1, buf, kk + 1);

            u64 b_pk[2] = { wb[p].x, wb[p].y };
            u64 a_pk[4] = { fdup(wa[p].x), fdup(wa[p].y),
                            fdup(wa[p].z), fdup(wa[p].w) };
            #pragma unroll
            for (int i = 0; i < 4; i++)
                #pragma unroll
                for (int jp = 0; jp < 2; jp++)
                    ffma2(acc2[i][jp], a_pk[i], b_pk[jp]);
        }

        if (has_next) WSTORE(buf ^ 1);
        __syncthreads();
        buf ^= 1;
    }
    #undef WLOAD
    #undef WSTORE
    #undef WFRAG

    #pragma unroll
    for (int i = 0; i < 4; i++) {
        const int r = row0 + ty * 4 + i;
        #pragma unroll
        for (int jp = 0; jp < 2; jp++) {
            float2 yv = funpack(acc2[i][jp]);
            #pragma unroll
            for (int l = 0; l < 2; l++) {
                const int col = bx * WBN + tx * 4 + jp * 2 + l;
                const size_t idx = (size_t)r * DIM + col;
                C[idx] = addv[idx] + ((l == 0) ? yv.x : yv.y);
            }
        }
    }
}

// ---------------------------------------------------------------------------
// gate = (c1/10) * ((c3p - c3n)/10)
// ---------------------------------------------------------------------------
__global__ void gate_kernel(const float* __restrict__ c1,
                            const float* __restrict__ c3p,
                            const float* __restrict__ c3n,
                            float* __restrict__ g)
{
    const int i = blockIdx.x * blockDim.x + threadIdx.x;
    if (i < NTOK * HIDDEN)
        g[i] = (c1[i] / 10.0f) * ((c3p[i] - c3n[i]) / 10.0f);
}

// ---------------------------------------------------------------------------
// Spike attention (bit-frozen)
// ---------------------------------------------------------------------------
__global__ void attn_kernel(const unsigned* __restrict__ qm,
                            const unsigned* __restrict__ km,
                            const unsigned* __restrict__ vm,
                            float* __restrict__ xat)
{
    __shared__ unsigned sq[128 * 33];
    __shared__ unsigned sk[128 * 9];
    __shared__ unsigned sv[8 * 128];
    __shared__ int      S[NHEAD * 8];

    const int n   = blockIdx.x;
    const int tid = threadIdx.x;

    for (int idx = tid; idx < NHEAD * HDIM; idx += 128) {
        const int i = idx >> 7, d = idx & 127;
        sq[d * 33 + i] = qm[(size_t)n * DIM + idx] | (qm[(size_t)(n + NTOK) * DIM + idx] << 16);
    }
    for (int idx = tid; idx < 8 * HDIM; idx += 128) {
        const int j = idx >> 7, d = idx & 127;
        sk[d * 9 + j] = km[(size_t)n * KVDIM + idx] | (km[(size_t)(n + NTOK) * KVDIM + idx] << 16);
        sv[idx]       = vm[(size_t)n * KVDIM + idx] | (vm[(size_t)(n + NTOK) * KVDIM + idx] << 16);
    }
    __syncthreads();

    for (int t = 0; t < TSTEPS; t++) {
        #pragma unroll
        for (int e0 = 0; e0 < 2; e0++) {
            const int e = tid + e0 * 128;
            const int i = e >> 3, j = e & 7;
            int s = 0;
            for (int d2 = 0; d2 < HDIM; d2++) {
                const unsigned q = sq[d2 * 33 + i];
                const unsigned k = sk[d2 * 9 + j];
                const int qv = (int)((q >> t) & 1u) - (int)((q >> (t + 16)) & 1u);
                const int kv = (int)((k >> t) & 1u) - (int)((k >> (t + 16)) & 1u);
                s += qv * kv;
            }
            S[e] = s;
        }
        __syncthreads();

        {
            const int d2 = tid;
            int vv[8];
            #pragma unroll
            for (int j = 0; j < 8; j++) {
                const unsigned v = sv[j * 128 + d2];
                vv[j] = (int)((v >> t) & 1u) - (int)((v >> (t + 16)) & 1u);
            }
            float* orow = xat + ((size_t)t * NTOK + n) * DIM + (size_t)d2 * NHEAD;
            #pragma unroll
            for (int i = 0; i < NHEAD; i++) {
                int s = 0;
                #pragma unroll
                for (int j = 0; j < 8; j++) s += S[i * 8 + j] * vv[j];
                orow[i] = (float)s * 0.5f;
            }
        }
        __syncthreads();
    }
}

// ---------------------------------------------------------------------------
// h = x + mean_t(y_t) (bit-frozen)
// ---------------------------------------------------------------------------
__global__ void wo_mean_kernel(const float* __restrict__ yt,
                               const float* __restrict__ x,
                               float* __restrict__ h)
{
    const int idx = blockIdx.x * blockDim.x + threadIdx.x;
    if (idx >= NTOK * DIM) return;
    float s = 0.f;
    #pragma unroll
    for (int t = 0; t < TSTEPS; t++)
        s += yt[(size_t)t * NTOK * DIM + idx];
    h[idx] = x[idx] + s / 10.0f;
}

// ---------------------------------------------------------------------------
// Launch
// ---------------------------------------------------------------------------
#define G2_SMEM (2 * BK2G * (BM2 + BN2) * (int)sizeof(float))   // 65536 bytes

extern "C" void kernel_launch(void* const* d_in, const int* in_sizes, int n_in,
                              void* d_out, int out_size)
{
    const float* x           = (const float*)d_in[0];
    const float* attn_norm_w = (const float*)d_in[2];
    const float* ffn_norm_w  = (const float*)d_in[3];
    const float* wq          = (const float*)d_in[4];
    const float* wk          = (const float*)d_in[5];
    const float* wv          = (const float*)d_in[6];
    const float* wo          = (const float*)d_in[7];
    const float* w1          = (const float*)d_in[8];
    const float* w2          = (const float*)d_in[9];
    const float* w3          = (const float*)d_in[10];
    float* out = (float*)d_out;

    // opt-in to 64KB dynamic smem (host-side attribute set; capture-safe)
    cudaFuncSetAttribute((const void*)gemm2_kernel<1>,
                         cudaFuncAttributeMaxDynamicSharedMemorySize, G2_SMEM);
    cudaFuncSetAttribute((const void*)gemm2_kernel<2>,
                         cudaFuncAttributeMaxDynamicSharedMemorySize, G2_SMEM);

    float *xs, *hs, *xat, *yt, *h, *c3, *c1, *gate;
    unsigned *qm, *km, *vm;
    cudaGetSymbolAddress((void**)&xs,   g_xs);
    cudaGetSymbolAddress((void**)&hs,   g_hs);
    cudaGetSymbolAddress((void**)&qm,   g_qm);
    cudaGetSymbolAddress((void**)&km,   g_km);
    cudaGetSymbolAddress((void**)&vm,   g_vm);
    cudaGetSymbolAddress((void**)&xat,  g_xat);
    cudaGetSymbolAddress((void**)&yt,   g_yt);
    cudaGetSymbolAddress((void**)&h,    g_h);
    cudaGetSymbolAddress((void**)&c3,   g_c3);
    cudaGetSymbolAddress((void**)&c1,   g_c1);
    cudaGetSymbolAddress((void**)&gate, g_gate);

    // 1) attn rmsnorm + stacked relu
    rmsnorm_relu_kernel<<<NTOK, 1024>>>(x, attn_norm_w, xs);

    // 2) fused QKV spike-mask projections (split-K=4, FFMA2 — R12 form)
    gemm_qkv_kernel<<<dim3(96, 4), 256>>>(xs, wq, wk, wv, qm, km, vm, DIM);

    // 3) exact spike attention -> per-timestep planes
    attn_kernel<<<NTOK, 128>>>(qm, km, vm, xat);

    // 4) per-t wo GEMM: yt = xat @ wo^T  (BK=32, halved barriers)
    gemm2_kernel<2><<<dim3(32, 20), 256, G2_SMEM>>>(xat, wo, nullptr, yt, nullptr, DIM);

    // 5) h = x + mean_t(y_t)
    wo_mean_kernel<<<(NTOK * DIM + 255) / 256, 256>>>(yt, x, h);

    // 6) ffn rmsnorm + stacked relu
    rmsnorm_relu_kernel<<<NTOK, 1024>>>(h, ffn_norm_w, hs);

    // 7) fused FFN spike-count projections: w3 (M=512) + w1 (M=256)
    gemm2_kernel<1><<<dim3(112, 6), 256, G2_SMEM>>>(hs, w3, w1, c3, c1, DIM);

    // 8) gate (elementwise)
    gate_kernel<<<(NTOK * HIDDEN + 255) / 256, 256>>>(c1, c3, c3 + (size_t)NTOK * HIDDEN, gate);

    // 9) out = h + gate @ w2^T  (frag-pipelined)
    gemm_w2_kernel<<<dim3(64, 4), 256>>>(gate, w2, out, h, HIDDEN);
}

// round 16
// speedup vs baseline: 1.0776x; 1.0776x over previous
#include <cuda_runtime.h>
#include <cstdint>

// ---------------------------------------------------------------------------
// Problem constants
// ---------------------------------------------------------------------------
#define NTOK   256
#define DIM    4096
#define HIDDEN 14336
#define KVDIM  1024
#define NHEAD  32
#define HDIM   128
#define TSTEPS 10

typedef unsigned long long u64;

// ---------------------------------------------------------------------------
// Packed f32x2 helpers (sm_103a FFMA2 path — only reachable via PTX).
// ---------------------------------------------------------------------------
__device__ __forceinline__ u64 fdup(float a) {
    u64 r; asm("mov.b64 %0, {%1, %1};" : "=l"(r) : "f"(a)); return r;
}
__device__ __forceinline__ void ffma2(u64& d, u64 a, u64 b) {
    asm("fma.rn.f32x2 %0, %1, %2, %0;" : "+l"(d) : "l"(a), "l"(b));
}
__device__ __forceinline__ void fadd2(u64& d, u64 a) {
    asm("add.rn.f32x2 %0, %0, %1;" : "+l"(d) : "l"(a));
}
__device__ __forceinline__ float2 funpack(u64 v) {
    float lo, hi; asm("mov.b64 {%0, %1}, %2;" : "=f"(lo), "=f"(hi) : "l"(v));
    return make_float2(lo, hi);
}

// ---------------------------------------------------------------------------
// Scratch (device globals)
// ---------------------------------------------------------------------------
__device__ float    g_xs [2 * NTOK * DIM];
__device__ float    g_hs [2 * NTOK * DIM];
__device__ unsigned g_qm [2 * NTOK * DIM];
__device__ unsigned g_km [2 * NTOK * KVDIM];
__device__ unsigned g_vm [2 * NTOK * KVDIM];
__device__ float    g_xat[TSTEPS * NTOK * DIM];
__device__ float    g_yt [TSTEPS * NTOK * DIM];
__device__ float    g_h  [NTOK * DIM];
__device__ float    g_c3 [2 * NTOK * HIDDEN];
__device__ float    g_c1 [NTOK * HIDDEN];
__device__ float    g_gate[NTOK * HIDDEN];

// ---------------------------------------------------------------------------
// RMSNorm + stacked relu. FUSE=false: plain (norm of x).
// FUSE=true: phase 1 computes h = x + (sum_t yt)/10 inline (ascending t,
// identical formula/order to the old wo_mean kernel -> bit-exact), writes h,
// accumulates squares of h; phase 2 reads h back for normalized outputs.
// ---------------------------------------------------------------------------
template<bool FUSE>
__global__ __launch_bounds__(1024)
void rmsnorm_relu_kernel(const float* __restrict__ x,
                         const float* __restrict__ yt,
                         float* __restrict__ hout,
                         const float* __restrict__ w,
                         float* __restrict__ out)
{
    const int n = blockIdx.x;
    const int t = threadIdx.x;
    const float* xr = x + (size_t)n * DIM;

    float acc = 0.f;
    #pragma unroll
    for (int i = 0; i < 2; i++) {
        const int c0 = 2 * t + i * 2048;
        float2 v = *(const float2*)(xr + c0);
        if (FUSE) {
            float s0 = 0.f, s1 = 0.f;
            #pragma unroll
            for (int tt = 0; tt < TSTEPS; tt++) {
                const float* yp = yt + (size_t)tt * NTOK * DIM + (size_t)n * DIM + c0;
                s0 += yp[0];
                s1 += yp[1];
            }
            v.x = v.x + s0 / 10.0f;
            v.y = v.y + s1 / 10.0f;
            *(float2*)(hout + (size_t)n * DIM + c0) = v;
        }
        acc += v.x * v.x;
        acc += v.y * v.y;
    }
    #pragma unroll
    for (int o = 16; o > 0; o >>= 1)
        acc += __shfl_down_sync(0xffffffffu, acc, o);

    __shared__ float sw[32];
    __shared__ float sres;
    const int lane = t & 31, wid = t >> 5;
    if (lane == 0) sw[wid] = acc;
    __syncthreads();
    if (wid == 0) {
        float v = sw[lane];
        #pragma unroll
        for (int o = 16; o > 0; o >>= 1)
            v += __shfl_down_sync(0xffffffffu, v, o);
        if (lane == 0) sres = v;
    }
    __syncthreads();

    const float* src = FUSE ? (hout + (size_t)n * DIM) : xr;
    const float rs = rsqrtf(sres * (1.0f / 4096.0f) + 1e-5f);
    #pragma unroll
    for (int i = 0; i < 4; i++) {
        const int c = t + i * 1024;
        float v = src[c] * rs * w[c];
        out[(size_t)n * DIM + c]          = fmaxf(v, 0.f);
        out[(size_t)(n + NTOK) * DIM + c] = fmaxf(-v, 0.f);
    }
}

// ---------------------------------------------------------------------------
// QKV GEMM: split-K=4 emulation, FFMA2 (exact R12 form — bit-frozen).
// ---------------------------------------------------------------------------
#define QBM 128
#define QBN 64
#define QBK 16
#define SPLITK_CHUNK 1024

__global__ __launch_bounds__(256, 2)
void gemm_qkv_kernel(const float* __restrict__ A,
                     const float* __restrict__ B0,
                     const float* __restrict__ B1,
                     const float* __restrict__ B2,
                     unsigned* __restrict__ C0, unsigned* __restrict__ C1,
                     unsigned* __restrict__ C2, int K)
{
    __shared__ float As[2][QBK][QBM];
    __shared__ float Bs[2][QBK][QBN];

    const int bx = blockIdx.x, by = blockIdx.y;
    const float* B; unsigned* C; int N, bxl;
    const int row0 = by * QBM;
    if (bx < 64)      { B = B0; C = C0; N = DIM;   bxl = bx; }
    else if (bx < 80) { B = B1; C = C1; N = KVDIM; bxl = bx - 64; }
    else              { B = B2; C = C2; N = KVDIM; bxl = bx - 80; }

    const int tid = threadIdx.x;
    const int tx = tid & 15;
    const int ty = tid >> 4;

    const int lrowA = tid >> 1;
    const int lcolA = (tid & 1) * 8;
    const int lrowB = tid >> 2;
    const int lcolB = (tid & 3) * 4;

    const float* Aptr = A + (size_t)(row0 + lrowA) * K + lcolA;
    const float* Bptr = B + (size_t)(bxl * QBN + lrowB) * K + lcolB;

    u64 acc2[8][2], tot2[8][2];
    #pragma unroll
    for (int i = 0; i < 8; i++)
        #pragma unroll
        for (int j = 0; j < 2; j++) { acc2[i][j] = 0ULL; tot2[i][j] = 0ULL; }

    float4 a0s, a1s, b0s;
    #define QLOAD()                                                            \
        do {                                                                   \
            a0s = *(const float4*)Aptr;                                        \
            a1s = *(const float4*)(Aptr + 4);                                  \
            b0s = *(const float4*)Bptr;                                        \
            Aptr += QBK; Bptr += QBK;                                          \
        } while (0)
    #define QSTORE(BUF)                                                        \
        do {                                                                   \
            As[BUF][lcolA + 0][lrowA] = a0s.x; As[BUF][lcolA + 1][lrowA] = a0s.y; \
            As[BUF][lcolA + 2][lrowA] = a0s.z; As[BUF][lcolA + 3][lrowA] = a0s.w; \
            As[BUF][lcolA + 4][lrowA] = a1s.x; As[BUF][lcolA + 5][lrowA] = a1s.y; \
            As[BUF][lcolA + 6][lrowA] = a1s.z; As[BUF][lcolA + 7][lrowA] = a1s.w; \
            Bs[BUF][lcolB + 0][lrowB] = b0s.x; Bs[BUF][lcolB + 1][lrowB] = b0s.y; \
            Bs[BUF][lcolB + 2][lrowB] = b0s.z; Bs[BUF][lcolB + 3][lrowB] = b0s.w; \
        } while (0)

    QLOAD(); QSTORE(0);
    __syncthreads();

    int buf = 0;
    for (int k0 = 0; k0 < K; k0 += QBK) {
        const bool has_next = (k0 + QBK < K);
        if (has_next) QLOAD();

        #pragma unroll
        for (int kk = 0; kk < QBK; kk++) {
            float4 a0 = *(const float4*)&As[buf][kk][ty * 8];
            float4 a1 = *(const float4*)&As[buf][kk][ty * 8 + 4];
            ulonglong2 bp = *(const ulonglong2*)&Bs[buf][kk][tx * 4];
            u64 b_pk[2] = { bp.x, bp.y };
            u64 a_pk[8] = { fdup(a0.x), fdup(a0.y), fdup(a0.z), fdup(a0.w),
                            fdup(a1.x), fdup(a1.y), fdup(a1.z), fdup(a1.w) };
            #pragma unroll
            for (int i = 0; i < 8; i++)
                #pragma unroll
                for (int jp = 0; jp < 2; jp++)
                    ffma2(acc2[i][jp], a_pk[i], b_pk[jp]);
        }

        if (((k0 + QBK) & (SPLITK_CHUNK - 1)) == 0) {
            #pragma unroll
            for (int i = 0; i < 8; i++)
                #pragma unroll
                for (int jp = 0; jp < 2; jp++) {
                    fadd2(tot2[i][jp], acc2[i][jp]);
                    acc2[i][jp] = 0ULL;
                }
        }

        if (has_next) QSTORE(buf ^ 1);
        __syncthreads();
        buf ^= 1;
    }
    #undef QLOAD
    #undef QSTORE

    #pragma unroll
    for (int i = 0; i < 8; i++) {
        const int r = row0 + ty * 8 + i;
        #pragma unroll
        for (int jp = 0; jp < 2; jp++) {
            float2 yv = funpack(tot2[i][jp]);
            #pragma unroll
            for (int l = 0; l < 2; l++) {
                const int col = bxl * QBN + tx * 4 + jp * 2 + l;
                float y = (l == 0) ? yv.x : yv.y;
                unsigned m = 0; float vm = 0.f;
                #pragma unroll
                for (int t = 0; t < TSTEPS; t++) {
                    vm += y;
                    if (vm - 1.0f >= 0.f) { m |= (1u << t); vm = 0.f; }
                }
                C[(size_t)r * N + col] = m;
            }
        }
    }
}

// ---------------------------------------------------------------------------
// Big GEMM (NT), 128x128 tile, 8x8/thread, BK=16, static double-buffered smem,
// FFMA2, split frags + frag pipelining.  (EXACT R12 config — measured best.)
//   MODE 1: FFN spike counts (N=HIDDEN; by<4 -> w3/c3 M=512; else w1/c1 M=256)
//   MODE 2: plain f32 store (per-t wo GEMM, M=2560, N=DIM)
// ---------------------------------------------------------------------------
#define BM2 128
#define BN2 128
#define BK2 16

template<int MODE>
__global__ __launch_bounds__(256, 2)
void gemm2_kernel(const float* __restrict__ A,
                  const float* __restrict__ B0,
                  const float* __restrict__ B1,
                  void* __restrict__ C0, void* __restrict__ C1, int K)
{
    __shared__ float As[2][BK2][BM2];
    __shared__ float Bs[2][BK2][BN2];

    const int bx = blockIdx.x, by = blockIdx.y;
    const float* B; void* C; int N, row0;
    if (MODE == 1) {
        N = HIDDEN;
        if (by < 4) { B = B0; C = C0; row0 = by * BM2; }
        else        { B = B1; C = C1; row0 = (by - 4) * BM2; }
    } else {
        N = DIM; B = B0; C = C0; row0 = by * BM2;
    }

    const int tid = threadIdx.x;
    const int tx = tid & 15;
    const int ty = tid >> 4;
    const int lrow = tid >> 1;
    const int lcol = (tid & 1) * 8;

    const float* Aptr = A + (size_t)(row0 + lrow) * K + lcol;
    const float* Bptr = B + (size_t)(bx * BN2 + lrow) * K + lcol;

    u64 acc2[8][4];
    #pragma unroll
    for (int i = 0; i < 8; i++)
        #pragma unroll
        for (int jp = 0; jp < 4; jp++) acc2[i][jp] = 0ULL;

    float4 a0s, a1s, b0s, b1s;
    #define GLOAD()                                                            \
        do {                                                                   \
            a0s = *(const float4*)Aptr;                                        \
            a1s = *(const float4*)(Aptr + 4);                                  \
            b0s = *(const float4*)Bptr;                                        \
            b1s = *(const float4*)(Bptr + 4);                                  \
            Aptr += BK2; Bptr += BK2;                                          \
        } while (0)
    #define GSTORE(BUF)                                                        \
        do {                                                                   \
            As[BUF][lcol + 0][lrow] = a0s.x; As[BUF][lcol + 1][lrow] = a0s.y;  \
            As[BUF][lcol + 2][lrow] = a0s.z; As[BUF][lcol + 3][lrow] = a0s.w;  \
            As[BUF][lcol + 4][lrow] = a1s.x; As[BUF][lcol + 5][lrow] = a1s.y;  \
            As[BUF][lcol + 6][lrow] = a1s.z; As[BUF][lcol + 7][lrow] = a1s.w;  \
            Bs[BUF][lcol + 0][lrow] = b0s.x; Bs[BUF][lcol + 1][lrow] = b0s.y;  \
            Bs[BUF][lcol + 2][lrow] = b0s.z; Bs[BUF][lcol + 3][lrow] = b0s.w;  \
            Bs[BUF][lcol + 4][lrow] = b1s.x; Bs[BUF][lcol + 5][lrow] = b1s.y;  \
            Bs[BUF][lcol + 6][lrow] = b1s.z; Bs[BUF][lcol + 7][lrow] = b1s.w;  \
        } while (0)

    float4     fa0[2], fa1[2];
    ulonglong2 fb0[2], fb1[2];
    #define FRAG_LOAD(P, BUF, KK)                                              \
        do {                                                                   \
            fa0[P] = *(const float4*)&As[BUF][KK][ty * 4];                     \
            fa1[P] = *(const float4*)&As[BUF][KK][64 + ty * 4];                \
            fb0[P] = *(const ulonglong2*)&Bs[BUF][KK][tx * 4];                 \
            fb1[P] = *(const ulonglong2*)&Bs[BUF][KK][64 + tx * 4];            \
        } while (0)

    GLOAD(); GSTORE(0);
    __syncthreads();

    int buf = 0;
    for (int k0 = 0; k0 < K; k0 += BK2) {
        const bool has_next = (k0 + BK2 < K);
        if (has_next) GLOAD();

        FRAG_LOAD(0, buf, 0);
        #pragma unroll
        for (int kk = 0; kk < BK2; kk++) {
            const int p = kk & 1;
            if (kk + 1 < BK2) FRAG_LOAD(p ^ 1, buf, kk + 1);

            u64 b_pk[4] = { fb0[p].x, fb0[p].y, fb1[p].x, fb1[p].y };
            u64 a_pk[8] = { fdup(fa0[p].x), fdup(fa0[p].y),
                            fdup(fa0[p].z), fdup(fa0[p].w),
                            fdup(fa1[p].x), fdup(fa1[p].y),
                            fdup(fa1[p].z), fdup(fa1[p].w) };
            #pragma unroll
            for (int i = 0; i < 8; i++)
                #pragma unroll
                for (int jp = 0; jp < 4; jp++)
                    ffma2(acc2[i][jp], a_pk[i], b_pk[jp]);
        }

        if (has_next) GSTORE(buf ^ 1);
        __syncthreads();
        buf ^= 1;
    }
    #undef GLOAD
    #undef GSTORE
    #undef FRAG_LOAD

    #pragma unroll
    for (int i = 0; i < 8; i++) {
        const int r = row0 + ((i < 4) ? (ty * 4 + i) : (64 + ty * 4 + (i - 4)));
        #pragma unroll
        for (int jp = 0; jp < 4; jp++) {
            const int colbase = bx * BN2 +
                ((jp < 2) ? (tx * 4 + jp * 2) : (64 + tx * 4 + (jp - 2) * 2));
            float2 yv = funpack(acc2[i][jp]);
            #pragma unroll
            for (int l = 0; l < 2; l++) {
                const size_t idx = (size_t)r * N + colbase + l;
                float y = (l == 0) ? yv.x : yv.y;
                if (MODE == 1) {
                    int cnt = 0; float vm = 0.f;
                    #pragma unroll
                    for (int t = 0; t < TSTEPS; t++) {
                        vm += y;
                        if (vm - 1.0f >= 0.f) { cnt++; vm = 0.f; }
                    }
                    ((float*)C)[idx] = (float)cnt;
                } else {
                    ((float*)C)[idx] = y;
                }
            }
        }
    }
}

// ---------------------------------------------------------------------------
// w2 GEMM: 64x64 tile (256 CTAs), BK=32, 4x4/thread, FFMA2, frag-pipelined.
// ---------------------------------------------------------------------------
#define WBM 64
#define WBN 64
#define WBK 32

__global__ __launch_bounds__(256)
void gemm_w2_kernel(const float* __restrict__ A,
                    const float* __restrict__ B,
                    float* __restrict__ C,
                    const float* __restrict__ addv, int K)
{
    __shared__ float As[2][WBK][WBM];
    __shared__ float Bs[2][WBK][WBN];

    const int bx = blockIdx.x, by = blockIdx.y;
    const int row0 = by * WBM;
    const int tid = threadIdx.x;
    const int tx = tid & 15;
    const int ty = tid >> 4;
    const int lrow = tid >> 2;
    const int lcol = (tid & 3) * 8;

    const float* Aptr = A + (size_t)(row0 + lrow) * K + lcol;
    const float* Bptr = B + (size_t)(bx * WBN + lrow) * K + lcol;

    u64 acc2[4][2];
    #pragma unroll
    for (int i = 0; i < 4; i++)
        #pragma unroll
        for (int jp = 0; jp < 2; jp++) acc2[i][jp] = 0ULL;

    float4 a0s, a1s, b0s, b1s;
    #define WLOAD()                                                            \
        do {                                                                   \
            a0s = *(const float4*)Aptr;                                        \
            a1s = *(const float4*)(Aptr + 4);                                  \
            b0s = *(const float4*)Bptr;                                        \
            b1s = *(const float4*)(Bptr + 4);                                  \
            Aptr += WBK; Bptr += WBK;                                          \
        } while (0)
    #define WSTORE(BUF)                                                        \
        do {                                                                   \
            As[BUF][lcol + 0][lrow] = a0s.x; As[BUF][lcol + 1][lrow] = a0s.y;  \
            As[BUF][lcol + 2][lrow] = a0s.z; As[BUF][lcol + 3][lrow] = a0s.w;  \
            As[BUF][lcol + 4][lrow] = a1s.x; As[BUF][lcol + 5][lrow] = a1s.y;  \
            As[BUF][lcol + 6][lrow] = a1s.z; As[BUF][lcol + 7][lrow] = a1s.w;  \
            Bs[BUF][lcol + 0][lrow] = b0s.x; Bs[BUF][lcol + 1][lrow] = b0s.y;  \
            Bs[BUF][lcol + 2][lrow] = b0s.z; Bs[BUF][lcol + 3][lrow] = b0s.w;  \
            Bs[BUF][lcol + 4][lrow] = b1s.x; Bs[BUF][lcol + 5][lrow] = b1s.y;  \
            Bs[BUF][lcol + 6][lrow] = b1s.z; Bs[BUF][lcol + 7][lrow] = b1s.w;  \
        } while (0)

    float4     wa[2];
    ulonglong2 wb[2];
    #define WFRAG(P, BUF, KK)                                                  \
        do {                                                                   \
            wa[P] = *(const float4*)&As[BUF][KK][ty * 4];                      \
            wb[P] = *(const ulonglong2*)&Bs[BUF][KK][tx * 4];                  \
        } while (0)

    WLOAD(); WSTORE(0);
    __syncthreads();

    int buf = 0;
    for (int k0 = 0; k0 < K; k0 += WBK) {
        const bool has_next = (k0 + WBK < K);
        if (has_next) WLOAD();

        WFRAG(0, buf, 0);
        #pragma unroll
        for (int kk = 0; kk < WBK; kk++) {
            const int p = kk & 1;
            if (kk + 1 < WBK) WFRAG(p ^ 1, buf, kk + 1);

            u64 b_pk[2] = { wb[p].x, wb[p].y };
            u64 a_pk[4] = { fdup(wa[p].x), fdup(wa[p].y),
                            fdup(wa[p].z), fdup(wa[p].w) };
            #pragma unroll
            for (int i = 0; i < 4; i++)
                #pragma unroll
                for (int jp = 0; jp < 2; jp++)
                    ffma2(acc2[i][jp], a_pk[i], b_pk[jp]);
        }

        if (has_next) WSTORE(buf ^ 1);
        __syncthreads();
        buf ^= 1;
    }
    #undef WLOAD
    #undef WSTORE
    #undef WFRAG

    #pragma unroll
    for (int i = 0; i < 4; i++) {
        const int r = row0 + ty * 4 + i;
        #pragma unroll
        for (int jp = 0; jp < 2; jp++) {
            float2 yv = funpack(acc2[i][jp]);
            #pragma unroll
            for (int l = 0; l < 2; l++) {
                const int col = bx * WBN + tx * 4 + jp * 2 + l;
                const size_t idx = (size_t)r * DIM + col;
                C[idx] = addv[idx] + ((l == 0) ? yv.x : yv.y);
            }
        }
    }
}

// ---------------------------------------------------------------------------
// gate = (c1/10) * ((c3p - c3n)/10)
// ---------------------------------------------------------------------------
__global__ void gate_kernel(const float* __restrict__ c1,
                            const float* __restrict__ c3p,
                            const float* __restrict__ c3n,
                            float* __restrict__ g)
{
    const int i = blockIdx.x * blockDim.x + threadIdx.x;
    if (i < NTOK * HIDDEN)
        g[i] = (c1[i] / 10.0f) * ((c3p[i] - c3n[i]) / 10.0f);
}

// ---------------------------------------------------------------------------
// Spike attention (bit-frozen)
// ---------------------------------------------------------------------------
__global__ void attn_kernel(const unsigned* __restrict__ qm,
                            const unsigned* __restrict__ km,
                            const unsigned* __restrict__ vm,
                            float* __restrict__ xat)
{
    __shared__ unsigned sq[128 * 33];
    __shared__ unsigned sk[128 * 9];
    __shared__ unsigned sv[8 * 128];
    __shared__ int      S[NHEAD * 8];

    const int n   = blockIdx.x;
    const int tid = threadIdx.x;

    for (int idx = tid; idx < NHEAD * HDIM; idx += 128) {
        const int i = idx >> 7, d = idx & 127;
        sq[d * 33 + i] = qm[(size_t)n * DIM + idx] | (qm[(size_t)(n + NTOK) * DIM + idx] << 16);
    }
    for (int idx = tid; idx < 8 * HDIM; idx += 128) {
        const int j = idx >> 7, d = idx & 127;
        sk[d * 9 + j] = km[(size_t)n * KVDIM + idx] | (km[(size_t)(n + NTOK) * KVDIM + idx] << 16);
        sv[idx]       = vm[(size_t)n * KVDIM + idx] | (vm[(size_t)(n + NTOK) * KVDIM + idx] << 16);
    }
    __syncthreads();

    for (int t = 0; t < TSTEPS; t++) {
        #pragma unroll
        for (int e0 = 0; e0 < 2; e0++) {
            const int e = tid + e0 * 128;
            const int i = e >> 3, j = e & 7;
            int s = 0;
            for (int d2 = 0; d2 < HDIM; d2++) {
                const unsigned q = sq[d2 * 33 + i];
                const unsigned k = sk[d2 * 9 + j];
                const int qv = (int)((q >> t) & 1u) - (int)((q >> (t + 16)) & 1u);
                const int kv = (int)((k >> t) & 1u) - (int)((k >> (t + 16)) & 1u);
                s += qv * kv;
            }
            S[e] = s;
        }
        __syncthreads();

        {
            const int d2 = tid;
            int vv[8];
            #pragma unroll
            for (int j = 0; j < 8; j++) {
                const unsigned v = sv[j * 128 + d2];
                vv[j] = (int)((v >> t) & 1u) - (int)((v >> (t + 16)) & 1u);
            }
            float* orow = xat + ((size_t)t * NTOK + n) * DIM + (size_t)d2 * NHEAD;
            #pragma unroll
            for (int i = 0; i < NHEAD; i++) {
                int s = 0;
                #pragma unroll
                for (int j = 0; j < 8; j++) s += S[i * 8 + j] * vv[j];
                orow[i] = (float)s * 0.5f;
            }
        }
        __syncthreads();
    }
}

// ---------------------------------------------------------------------------
// Launch
// ---------------------------------------------------------------------------
extern "C" void kernel_launch(void* const* d_in, const int* in_sizes, int n_in,
                              void* d_out, int out_size)
{
    const float* x           = (const float*)d_in[0];
    const float* attn_norm_w = (const float*)d_in[2];
    const float* ffn_norm_w  = (const float*)d_in[3];
    const float* wq          = (const float*)d_in[4];
    const float* wk          = (const float*)d_in[5];
    const float* wv          = (const float*)d_in[6];
    const float* wo          = (const float*)d_in[7];
    const float* w1          = (const float*)d_in[8];
    const float* w2          = (const float*)d_in[9];
    const float* w3          = (const float*)d_in[10];
    float* out = (float*)d_out;

    float *xs, *hs, *xat, *yt, *h, *c3, *c1, *gate;
    unsigned *qm, *km, *vm;
    cudaGetSymbolAddress((void**)&xs,   g_xs);
    cudaGetSymbolAddress((void**)&hs,   g_hs);
    cudaGetSymbolAddress((void**)&qm,   g_qm);
    cudaGetSymbolAddress((void**)&km,   g_km);
    cudaGetSymbolAddress((void**)&vm,   g_vm);
    cudaGetSymbolAddress((void**)&xat,  g_xat);
    cudaGetSymbolAddress((void**)&yt,   g_yt);
    cudaGetSymbolAddress((void**)&h,    g_h);
    cudaGetSymbolAddress((void**)&c3,   g_c3);
    cudaGetSymbolAddress((void**)&c1,   g_c1);
    cudaGetSymbolAddress((void**)&gate, g_gate);

    // 1) attn rmsnorm + stacked relu
    rmsnorm_relu_kernel<false><<<NTOK, 1024>>>(x, nullptr, nullptr, attn_norm_w, xs);

    // 2) fused QKV spike-mask projections (split-K=4, FFMA2 — R12 form)
    gemm_qkv_kernel<<<dim3(96, 4), 256>>>(xs, wq, wk, wv, qm, km, vm, DIM);

    // 3) exact spike attention -> per-timestep planes
    attn_kernel<<<NTOK, 128>>>(qm, km, vm, xat);

    // 4) per-t wo GEMM: yt = xat @ wo^T  (R12 config)
    gemm2_kernel<2><<<dim3(32, 20), 256>>>(xat, wo, nullptr, yt, nullptr, DIM);

    // 5) fused: h = x + mean_t(yt); ffn rmsnorm + stacked relu
    rmsnorm_relu_kernel<true><<<NTOK, 1024>>>(x, yt, h, ffn_norm_w, hs);

    // 6) fused FFN spike-count projections: w3 (M=512) + w1 (M=256)
    gemm2_kernel<1><<<dim3(112, 6), 256>>>(hs, w3, w1, c3, c1, DIM);

    // 7) gate (elementwise)
    gate_kernel<<<(NTOK * HIDDEN + 255) / 256, 256>>>(c1, c3, c3 + (size_t)NTOK * HIDDEN, gate);

    // 8) out = h + gate @ w2^T  (frag-pipelined)
    gemm_w2_kernel<<<dim3(64, 4), 256>>>(gate, w2, out, h, HIDDEN);
}